// round 5
// baseline (speedup 1.0000x reference)
#include <cuda_runtime.h>
#include <math.h>
#include <stdint.h>

#define B_ 4
#define T_ 2048
#define C_ 1024
#define F_ 4096
#define MROWS (B_*T_)   // 8192

// ---------------- scratch (device globals; no allocation allowed) ----------
__device__ float g_x[(size_t)MROWS*C_];
__device__ float g_h[(size_t)MROWS*C_];
__device__ float g_qkv[(size_t)MROWS*3*C_];
__device__ float g_att[(size_t)B_*T_*T_];
__device__ float g_ao[(size_t)MROWS*C_];
__device__ float g_vt[(size_t)B_*C_*T_];   // v transposed per batch: [C_, T_]
__device__ float g_ff[(size_t)MROWS*F_];
// rounded-weight scratch
__device__ float g_wqkv[(size_t)8*3*C_*C_];
__device__ float g_wout[(size_t)8*C_*C_];
__device__ float g_wff0[(size_t)8*F_*C_];
__device__ float g_wff3[(size_t)8*C_*F_];

// ================= base-target PTX helpers (no sm_103a features) ==========
__device__ __forceinline__ uint32_t smem_u32(const void* p) {
    uint32_t a;
    asm("{ .reg .u64 t; cvta.to.shared.u64 t, %1; cvt.u32.u64 %0, t; }" : "=r"(a) : "l"(p));
    return a;
}
__device__ __forceinline__ void cp_async16(uint32_t saddr, const void* gptr) {
    asm volatile("cp.async.cg.shared.global [%0], [%1], 16;" :: "r"(saddr), "l"(gptr) : "memory");
}
#define CP_COMMIT()  asm volatile("cp.async.commit_group;" ::: "memory")
#define CP_WAIT(n)   asm volatile("cp.async.wait_group %0;" :: "n"(n) : "memory")

__device__ __forceinline__ void ldsm4(uint32_t& r0, uint32_t& r1, uint32_t& r2, uint32_t& r3,
                                      uint32_t addr) {
    asm volatile("ldmatrix.sync.aligned.m8n8.x4.shared.b16 {%0,%1,%2,%3}, [%4];"
                 : "=r"(r0), "=r"(r1), "=r"(r2), "=r"(r3) : "r"(addr));
}
__device__ __forceinline__ float rnd_tf32(float x) {
    uint32_t u = __float_as_uint(x);
    asm("cvt.rna.tf32.f32 %0, %0;" : "+r"(u));
    return __uint_as_float(u);
}
__device__ __forceinline__ void mma_tf32(float* d, const uint32_t* a, const uint32_t* b) {
    asm volatile("mma.sync.aligned.m16n8k8.row.col.f32.tf32.tf32.f32 "
                 "{%0,%1,%2,%3}, {%4,%5,%6,%7}, {%8,%9}, {%0,%1,%2,%3};"
                 : "+f"(d[0]), "+f"(d[1]), "+f"(d[2]), "+f"(d[3])
                 : "r"(a[0]), "r"(a[1]), "r"(a[2]), "r"(a[3]), "r"(b[0]), "r"(b[1]));
}

#define NSTG 3
#define STAGE_BYTES 49152           // 16KB A + 32KB B
#define GEMM_SMEM_BYTES (NSTG * STAGE_BYTES)

// ============== tf32 mma.sync NT GEMM: D = A[M,K] * B[N,K]^T ==============
// CTA tile 128(M) x 256(N); warp tile 64x64 (2 M-warps x 4 N-warps).
// Inputs A,B must already be tf32-rounded.
// EPI: 0 = D=acc+bias ; 1 = D=gelu(acc+bias) ; 2 = D += acc+bias ; 3 = D=acc*alpha
// CSKIP: skip tiles fully above causal diagonal. CK: clip K at m0+128.
// RND: round stored result to tf32.
template<int EPI, bool CSKIP, bool CK, bool RND>
__global__ void __launch_bounds__(256) tc_gemm(
    const float* __restrict__ A, const float* __restrict__ B,
    const float* __restrict__ bias, float* __restrict__ C,
    int K, int lda, int ldb, int ldc,
    long long sA, long long sB, long long sC, float alpha)
{
    extern __shared__ __align__(1024) char smem[];
    const int m0 = blockIdx.y * 128;
    const int n0 = blockIdx.x * 256;
    if (CSKIP && n0 > m0 + 127) return;
    A += (long long)blockIdx.z * sA;
    B += (long long)blockIdx.z * sB;
    C += (long long)blockIdx.z * sC;

    const int tid = threadIdx.x;
    const int lane = tid & 31;
    const int wid = tid >> 5;
    const int warp_m = wid & 1;        // 2 warps over M (64 rows each)
    const int warp_n = wid >> 1;       // 4 warps over N (64 cols each)
    const uint32_t sbase = smem_u32(smem);

    const int kEnd = CK ? min(K, m0 + 128) : K;
    const int ktiles = kEnd >> 5;      // chunks of 32

    auto issue_tile = [&](int kt) {
        if (kt < ktiles) {
            const int k0 = kt << 5;
            const uint32_t stg = sbase + (uint32_t)(kt % NSTG) * STAGE_BYTES;
            // A: 128 rows x 128B = 1024 chunks (4 per thread)
            #pragma unroll
            for (int r = 0; r < 4; r++) {
                int f = tid + (r << 8);
                int row = f >> 3, c = f & 7;
                uint32_t soff = ((uint32_t)row << 7) + ((uint32_t)(c ^ (row & 7)) << 4);
                cp_async16(stg + soff,
                           A + (long long)(m0 + row) * lda + k0 + (c << 2));
            }
            // B: 256 rows x 128B = 2048 chunks (8 per thread)
            #pragma unroll
            for (int r = 0; r < 8; r++) {
                int f = tid + (r << 8);
                int row = f >> 3, c = f & 7;
                uint32_t soff = ((uint32_t)row << 7) + ((uint32_t)(c ^ (row & 7)) << 4);
                cp_async16(stg + 16384 + soff,
                           B + (long long)(n0 + row) * ldb + k0 + (c << 2));
            }
        }
        CP_COMMIT();
    };

    float acc[4][8][4];
    #pragma unroll
    for (int i = 0; i < 4; i++)
        #pragma unroll
        for (int j = 0; j < 8; j++)
            #pragma unroll
            for (int q = 0; q < 4; q++) acc[i][j][q] = 0.f;

    const int x7 = lane & 7;
    const int aRowL = ((lane >> 3) & 1) * 8 + x7;
    const int aChunk0 = (lane >> 4);
    const int bRowL = (lane >> 4) * 8 + x7;
    const int bChunk0 = (lane >> 3) & 1;

    issue_tile(0);
    issue_tile(1);

    for (int kt = 0; kt < ktiles; kt++) {
        CP_WAIT(1);
        __syncthreads();
        issue_tile(kt + 2);

        const uint32_t stgA = sbase + (uint32_t)(kt % NSTG) * STAGE_BYTES;
        const uint32_t stgB = stgA + 16384;

        #pragma unroll
        for (int ks = 0; ks < 4; ks++) {
            uint32_t af[4][4];
            #pragma unroll
            for (int mi = 0; mi < 4; mi++) {
                int row = warp_m * 64 + mi * 16 + aRowL;
                uint32_t addr = stgA + ((uint32_t)row << 7)
                              + ((uint32_t)((ks * 2 + aChunk0) ^ x7) << 4);
                ldsm4(af[mi][0], af[mi][1], af[mi][2], af[mi][3], addr);
            }
            uint32_t bf[8][2];
            #pragma unroll
            for (int nb = 0; nb < 4; nb++) {
                int row = warp_n * 64 + nb * 16 + bRowL;
                uint32_t addr = stgB + ((uint32_t)row << 7)
                              + ((uint32_t)((ks * 2 + bChunk0) ^ x7) << 4);
                uint32_t r0, r1, r2, r3;
                ldsm4(r0, r1, r2, r3, addr);
                bf[nb * 2][0] = r0; bf[nb * 2][1] = r1;
                bf[nb * 2 + 1][0] = r2; bf[nb * 2 + 1][1] = r3;
            }
            #pragma unroll
            for (int mi = 0; mi < 4; mi++)
                #pragma unroll
                for (int ni = 0; ni < 8; ni++)
                    mma_tf32(acc[mi][ni], af[mi], bf[ni]);
        }
    }

    // ---- epilogue ----
    const int erow = lane >> 2;
    const int ecol = 2 * (lane & 3);
    #pragma unroll
    for (int mi = 0; mi < 4; mi++) {
        #pragma unroll
        for (int ni = 0; ni < 8; ni++) {
            int mbase = m0 + warp_m * 64 + mi * 16 + erow;
            int nn = n0 + warp_n * 64 + ni * 8 + ecol;
            #pragma unroll
            for (int h = 0; h < 2; h++) {
                int m = mbase + h * 8;
                float v0 = acc[mi][ni][h * 2 + 0];
                float v1 = acc[mi][ni][h * 2 + 1];
                if (EPI == 3) {
                    v0 *= alpha; v1 *= alpha;
                } else {
                    float2 bb = *(const float2*)(bias + nn);
                    v0 += bb.x; v1 += bb.y;
                    if (EPI == 1) {
                        v0 = 0.5f * v0 * (1.0f + erff(v0 * 0.70710678118654752f));
                        v1 = 0.5f * v1 * (1.0f + erff(v1 * 0.70710678118654752f));
                    }
                }
                float* cp = C + (long long)m * ldc + nn;
                if (EPI == 2) {
                    float2 cv = *(const float2*)cp;
                    v0 += cv.x; v1 += cv.y;
                }
                if (RND) { v0 = rnd_tf32(v0); v1 = rnd_tf32(v1); }
                float2 o; o.x = v0; o.y = v1;
                *(float2*)cp = o;
            }
        }
    }
}

// ---------------- elementwise / reductions ----------------
__device__ __forceinline__ float warpSum(float v) {
    #pragma unroll
    for (int o = 16; o > 0; o >>= 1) v += __shfl_xor_sync(0xffffffffu, v, o);
    return v;
}
__device__ __forceinline__ float warpMax(float v) {
    #pragma unroll
    for (int o = 16; o > 0; o >>= 1) v = fmaxf(v, __shfl_xor_sync(0xffffffffu, v, o));
    return v;
}
__device__ __forceinline__ float blockSum(float v) {
    __shared__ float sh[8];
    int w = threadIdx.x >> 5, l = threadIdx.x & 31;
    v = warpSum(v);
    __syncthreads();
    if (l == 0) sh[w] = v;
    __syncthreads();
    float t = 0.f;
    #pragma unroll
    for (int i = 0; i < 8; i++) t += sh[i];
    return t;
}
__device__ __forceinline__ float blockMax(float v) {
    __shared__ float sh[8];
    int w = threadIdx.x >> 5, l = threadIdx.x & 31;
    v = warpMax(v);
    __syncthreads();
    if (l == 0) sh[w] = v;
    __syncthreads();
    float t = -INFINITY;
    #pragma unroll
    for (int i = 0; i < 8; i++) t = fmaxf(t, sh[i]);
    return t;
}

__global__ void copy4_kernel(const float4* __restrict__ src, float4* __restrict__ dst, int n4) {
    int i = blockIdx.x * 256 + threadIdx.x;
    if (i < n4) dst[i] = src[i];
}

// round float4 stream to tf32 (for weights)
__global__ void round4_kernel(const float4* __restrict__ src, float4* __restrict__ dst, int n4) {
    int i = blockIdx.x * 256 + threadIdx.x;
    if (i < n4) {
        float4 v = src[i];
        v.x = rnd_tf32(v.x); v.y = rnd_tf32(v.y);
        v.z = rnd_tf32(v.z); v.w = rnd_tf32(v.w);
        dst[i] = v;
    }
}

__global__ void __launch_bounds__(256) ln_kernel(
    const float* __restrict__ x, const float* __restrict__ w,
    const float* __restrict__ b, float* __restrict__ out)
{
    size_t row = blockIdx.x;
    const float4* xr = (const float4*)(x + row * C_);
    int tid = threadIdx.x;
    float4 v = xr[tid];
    float s = blockSum(v.x + v.y + v.z + v.w);
    float mean = s * (1.0f / C_);
    float d0 = v.x - mean, d1 = v.y - mean, d2 = v.z - mean, d3 = v.w - mean;
    float q = blockSum(d0*d0 + d1*d1 + d2*d2 + d3*d3);
    float inv = rsqrtf(q * (1.0f / C_) + 1e-5f);
    float4 wv = ((const float4*)w)[tid];
    float4 bv = ((const float4*)b)[tid];
    float4 o;
    o.x = rnd_tf32(d0 * inv * wv.x + bv.x);
    o.y = rnd_tf32(d1 * inv * wv.y + bv.y);
    o.z = rnd_tf32(d2 * inv * wv.z + bv.z);
    o.w = rnd_tf32(d3 * inv * wv.w + bv.w);
    ((float4*)(out + row * C_))[tid] = o;
}

__global__ void __launch_bounds__(256) softmax_kernel(float* __restrict__ att)
{
    int r = blockIdx.x;
    int b = r >> 11;
    int t = r & (T_ - 1);
    float* row = att + ((size_t)b * T_ + t) * T_;
    int n = t + 1;
    int tid = threadIdx.x;
    float vals[8];
    float vmax = -INFINITY;
    #pragma unroll
    for (int it = 0; it < 8; it++) {
        int i = tid + it * 256;
        vals[it] = (i < n) ? row[i] : -INFINITY;
        vmax = fmaxf(vmax, vals[it]);
    }
    vmax = blockMax(vmax);
    float s = 0.f;
    #pragma unroll
    for (int it = 0; it < 8; it++) {
        int i = tid + it * 256;
        if (i < n) { vals[it] = expf(vals[it] - vmax); s += vals[it]; }
        else vals[it] = 0.f;
    }
    s = blockSum(s);
    float inv = 1.0f / s;
    #pragma unroll
    for (int it = 0; it < 8; it++) {
        row[tid + it * 256] = rnd_tf32(vals[it] * inv);   // zeros stay zero
    }
}

// v[b][t][c] (inside qkv, offset 2C, row stride 3C) -> vt[b][c][t]
__global__ void transpose_v_kernel(const float* __restrict__ qkv, float* __restrict__ vt)
{
    __shared__ float tile[32][33];
    int b = blockIdx.z;
    int t0 = blockIdx.x * 32, c0 = blockIdx.y * 32;
    int tx = threadIdx.x, ty = threadIdx.y;   // 32 x 8
    #pragma unroll
    for (int r = 0; r < 32; r += 8)
        tile[ty + r][tx] = qkv[((long long)b * T_ + t0 + ty + r) * 3 * C_ + 2 * C_ + c0 + tx];
    __syncthreads();
    #pragma unroll
    for (int r = 0; r < 32; r += 8)
        vt[((long long)b * C_ + c0 + ty + r) * T_ + t0 + tx] = tile[tx][ty + r];
}

// ---------------- host launcher ----------------
extern "C" void kernel_launch(void* const* d_in, const int* in_sizes, int n_in,
                              void* d_out, int out_size)
{
    const float* x     = (const float*)d_in[0];
    const float* ln1_w = (const float*)d_in[1];
    const float* ln1_b = (const float*)d_in[2];
    const float* qkv_w = (const float*)d_in[3];
    const float* qkv_b = (const float*)d_in[4];
    const float* out_w = (const float*)d_in[5];
    const float* out_b = (const float*)d_in[6];
    const float* ln2_w = (const float*)d_in[7];
    const float* ln2_b = (const float*)d_in[8];
    const float* ff0_w = (const float*)d_in[9];
    const float* ff0_b = (const float*)d_in[10];
    const float* ff3_w = (const float*)d_in[11];
    const float* ff3_b = (const float*)d_in[12];

    float *gx, *gh, *gqkv, *gatt, *gao, *gvt, *gff;
    float *wqkv, *wout, *wff0, *wff3;
    cudaGetSymbolAddress((void**)&gx,   g_x);
    cudaGetSymbolAddress((void**)&gh,   g_h);
    cudaGetSymbolAddress((void**)&gqkv, g_qkv);
    cudaGetSymbolAddress((void**)&gatt, g_att);
    cudaGetSymbolAddress((void**)&gao,  g_ao);
    cudaGetSymbolAddress((void**)&gvt,  g_vt);
    cudaGetSymbolAddress((void**)&gff,  g_ff);
    cudaGetSymbolAddress((void**)&wqkv, g_wqkv);
    cudaGetSymbolAddress((void**)&wout, g_wout);
    cudaGetSymbolAddress((void**)&wff0, g_wff0);
    cudaGetSymbolAddress((void**)&wff3, g_wff3);

    cudaFuncSetAttribute(tc_gemm<0,false,false,true>,  cudaFuncAttributeMaxDynamicSharedMemorySize, GEMM_SMEM_BYTES);
    cudaFuncSetAttribute(tc_gemm<1,false,false,true>,  cudaFuncAttributeMaxDynamicSharedMemorySize, GEMM_SMEM_BYTES);
    cudaFuncSetAttribute(tc_gemm<2,false,false,false>, cudaFuncAttributeMaxDynamicSharedMemorySize, GEMM_SMEM_BYTES);
    cudaFuncSetAttribute(tc_gemm<3,true,false,false>,  cudaFuncAttributeMaxDynamicSharedMemorySize, GEMM_SMEM_BYTES);
    cudaFuncSetAttribute(tc_gemm<3,false,true,true>,   cudaFuncAttributeMaxDynamicSharedMemorySize, GEMM_SMEM_BYTES);

    // round all weights to tf32 once per launch
    {
        int n;
        n = 8 * 3 * C_ * C_ / 4; round4_kernel<<<(n + 255) / 256, 256>>>((const float4*)qkv_w, (float4*)wqkv, n);
        n = 8 * C_ * C_ / 4;     round4_kernel<<<(n + 255) / 256, 256>>>((const float4*)out_w, (float4*)wout, n);
        n = 8 * F_ * C_ / 4;     round4_kernel<<<(n + 255) / 256, 256>>>((const float4*)ff0_w, (float4*)wff0, n);
        n = 8 * C_ * F_ / 4;     round4_kernel<<<(n + 255) / 256, 256>>>((const float4*)ff3_w, (float4*)wff3, n);
    }

    const int n4 = MROWS * C_ / 4;
    copy4_kernel<<<(n4 + 255) / 256, 256>>>((const float4*)x, (float4*)gx, n4);

    const float scale = 0.03125f;   // 1/sqrt(1024)

    for (int i = 0; i < 8; i++) {
        // LN1 (rounded output)
        ln_kernel<<<MROWS, 256>>>(gx, ln1_w + (size_t)i * C_, ln1_b + (size_t)i * C_, gh);
        // qkv = h @ qkv_w^T + qkv_b  (rounded output)
        tc_gemm<0,false,false,true><<<dim3(3*C_/256, MROWS/128), 256, GEMM_SMEM_BYTES>>>(
            gh, wqkv + (size_t)i * 3 * C_ * C_, qkv_b + (size_t)i * 3 * C_, gqkv,
            C_, C_, C_, 3*C_, 0, 0, 0, 1.0f);
        // scores = (q @ k^T) * scale  (softmax rounds later)
        tc_gemm<3,true,false,false><<<dim3(T_/256, T_/128, B_), 256, GEMM_SMEM_BYTES>>>(
            gqkv, gqkv + C_, (const float*)0, gatt,
            C_, 3*C_, 3*C_, T_,
            (long long)T_ * 3 * C_, (long long)T_ * 3 * C_, (long long)T_ * T_, scale);
        // causal softmax (rounded output, zeros above diagonal)
        softmax_kernel<<<MROWS, 256>>>(gatt);
        // v^T per batch (input already rounded)
        transpose_v_kernel<<<dim3(T_/32, C_/32, B_), dim3(32, 8)>>>(gqkv, gvt);
        // ao = att @ v  (NT with B=vt, K clipped; rounded output)
        tc_gemm<3,false,true,true><<<dim3(C_/256, T_/128, B_), 256, GEMM_SMEM_BYTES>>>(
            gatt, gvt, (const float*)0, gao,
            T_, T_, T_, C_,
            (long long)T_ * T_, (long long)C_ * T_, (long long)T_ * C_, 1.0f);
        // x += ao @ out_w^T + out_b  (full fp32 residual)
        tc_gemm<2,false,false,false><<<dim3(C_/256, MROWS/128), 256, GEMM_SMEM_BYTES>>>(
            gao, wout + (size_t)i * C_ * C_, out_b + (size_t)i * C_, gx,
            C_, C_, C_, C_, 0, 0, 0, 1.0f);
        // LN2 (rounded output)
        ln_kernel<<<MROWS, 256>>>(gx, ln2_w + (size_t)i * C_, ln2_b + (size_t)i * C_, gh);
        // ff = gelu(h2 @ ff0_w^T + ff0_b)  (rounded output)
        tc_gemm<1,false,false,true><<<dim3(F_/256, MROWS/128), 256, GEMM_SMEM_BYTES>>>(
            gh, wff0 + (size_t)i * F_ * C_, ff0_b + (size_t)i * F_, gff,
            C_, C_, C_, F_, 0, 0, 0, 1.0f);
        // x += ff @ ff3_w^T + ff3_b  (full fp32 residual)
        tc_gemm<2,false,false,false><<<dim3(C_/256, MROWS/128), 256, GEMM_SMEM_BYTES>>>(
            gff, wff3 + (size_t)i * C_ * F_, ff3_b + (size_t)i * C_, gx,
            F_, F_, F_, C_, 0, 0, 0, 1.0f);
    }

    copy4_kernel<<<(n4 + 255) / 256, 256>>>((const float4*)gx, (float4*)d_out, n4);
}

// round 6
// speedup vs baseline: 1.2371x; 1.2371x over previous
#include <cuda_runtime.h>
#include <math.h>
#include <stdint.h>

#define B_ 4
#define T_ 2048
#define C_ 1024
#define F_ 4096
#define MROWS (B_*T_)   // 8192

// ---------------- scratch (device globals; no allocation allowed) ----------
__device__ float g_x[(size_t)MROWS*C_];
__device__ float g_h[(size_t)MROWS*C_];
__device__ float g_qkv[(size_t)MROWS*3*C_];
__device__ float g_att[(size_t)B_*T_*T_];
__device__ float g_ao[(size_t)MROWS*C_];
__device__ float g_vt[(size_t)B_*C_*T_];   // v transposed per batch: [C_, T_]
__device__ float g_ff[(size_t)MROWS*F_];
// rounded-weight scratch
__device__ float g_wqkv[(size_t)8*3*C_*C_];
__device__ float g_wout[(size_t)8*C_*C_];
__device__ float g_wff0[(size_t)8*F_*C_];
__device__ float g_wff3[(size_t)8*C_*F_];

// ================= base-target PTX helpers (no sm_103a features) ==========
__device__ __forceinline__ uint32_t smem_u32(const void* p) {
    uint32_t a;
    asm("{ .reg .u64 t; cvta.to.shared.u64 t, %1; cvt.u32.u64 %0, t; }" : "=r"(a) : "l"(p));
    return a;
}
__device__ __forceinline__ void cp_async16(uint32_t saddr, const void* gptr) {
    asm volatile("cp.async.cg.shared.global [%0], [%1], 16;" :: "r"(saddr), "l"(gptr) : "memory");
}
#define CP_COMMIT()  asm volatile("cp.async.commit_group;" ::: "memory")
#define CP_WAIT(n)   asm volatile("cp.async.wait_group %0;" :: "n"(n) : "memory")

__device__ __forceinline__ void ldsm4(uint32_t& r0, uint32_t& r1, uint32_t& r2, uint32_t& r3,
                                      uint32_t addr) {
    asm volatile("ldmatrix.sync.aligned.m8n8.x4.shared.b16 {%0,%1,%2,%3}, [%4];"
                 : "=r"(r0), "=r"(r1), "=r"(r2), "=r"(r3) : "r"(addr));
}
__device__ __forceinline__ float rnd_tf32(float x) {
    uint32_t u = __float_as_uint(x);
    asm("cvt.rna.tf32.f32 %0, %0;" : "+r"(u));
    return __uint_as_float(u);
}
__device__ __forceinline__ void mma_tf32(float* d, const uint32_t* a, const uint32_t* b) {
    asm volatile("mma.sync.aligned.m16n8k8.row.col.f32.tf32.tf32.f32 "
                 "{%0,%1,%2,%3}, {%4,%5,%6,%7}, {%8,%9}, {%0,%1,%2,%3};"
                 : "+f"(d[0]), "+f"(d[1]), "+f"(d[2]), "+f"(d[3])
                 : "r"(a[0]), "r"(a[1]), "r"(a[2]), "r"(a[3]), "r"(b[0]), "r"(b[1]));
}

#define NSTG 3
#define STAGE_BYTES 32768           // 16KB A + 16KB B
#define GEMM_SMEM_BYTES (NSTG * STAGE_BYTES)

// ============== tf32 mma.sync NT GEMM: D = A[M,K] * B[N,K]^T ==============
// CTA tile 128x128; 4 warps (2 over M x 2 over N), warp tile 64x64.
// Inputs A,B must already be tf32-rounded.
// EPI: 0 = D=acc+bias ; 1 = D=gelu(acc+bias) ; 2 = D += acc+bias ; 3 = D=acc*alpha
// CSKIP: skip tiles fully above causal diagonal. CK: clip K at m0+128.
// RND: round stored result to tf32.
template<int EPI, bool CSKIP, bool CK, bool RND>
__global__ void __launch_bounds__(128) tc_gemm(
    const float* __restrict__ A, const float* __restrict__ B,
    const float* __restrict__ bias, float* __restrict__ C,
    int K, int lda, int ldb, int ldc,
    long long sA, long long sB, long long sC, float alpha)
{
    extern __shared__ __align__(1024) char smem[];
    const int m0 = blockIdx.y * 128;
    const int n0 = blockIdx.x * 128;
    if (CSKIP && n0 > m0 + 127) return;
    A += (long long)blockIdx.z * sA;
    B += (long long)blockIdx.z * sB;
    C += (long long)blockIdx.z * sC;

    const int tid = threadIdx.x;
    const int lane = tid & 31;
    const int wid = tid >> 5;          // 0..3
    const int warp_m = wid & 1;        // 2 warps over M (64 rows each)
    const int warp_n = wid >> 1;       // 2 warps over N (64 cols each)
    const uint32_t sbase = smem_u32(smem);

    const int kEnd = CK ? min(K, m0 + 128) : K;
    const int ktiles = kEnd >> 5;      // chunks of 32

    auto issue_tile = [&](int kt) {
        if (kt < ktiles) {
            const int k0 = kt << 5;
            const uint32_t stg = sbase + (uint32_t)(kt % NSTG) * STAGE_BYTES;
            // A and B: each 128 rows x 8 16B-chunks = 1024 chunks, 8 per thread
            #pragma unroll
            for (int r = 0; r < 8; r++) {
                int f = tid + (r << 7);
                int row = f >> 3, c = f & 7;
                uint32_t soff = ((uint32_t)row << 7) + ((uint32_t)(c ^ (row & 7)) << 4);
                cp_async16(stg + soff,
                           A + (long long)(m0 + row) * lda + k0 + (c << 2));
                cp_async16(stg + 16384 + soff,
                           B + (long long)(n0 + row) * ldb + k0 + (c << 2));
            }
        }
        CP_COMMIT();
    };

    float acc[4][8][4];
    #pragma unroll
    for (int i = 0; i < 4; i++)
        #pragma unroll
        for (int j = 0; j < 8; j++)
            #pragma unroll
            for (int q = 0; q < 4; q++) acc[i][j][q] = 0.f;

    const int x7 = lane & 7;
    const int aRowL = ((lane >> 3) & 1) * 8 + x7;
    const int aChunk0 = (lane >> 4);
    const int bRowL = (lane >> 4) * 8 + x7;
    const int bChunk0 = (lane >> 3) & 1;

    issue_tile(0);
    issue_tile(1);

    for (int kt = 0; kt < ktiles; kt++) {
        CP_WAIT(1);
        __syncthreads();
        issue_tile(kt + 2);

        const uint32_t stgA = sbase + (uint32_t)(kt % NSTG) * STAGE_BYTES;
        const uint32_t stgB = stgA + 16384;

        #pragma unroll
        for (int ks = 0; ks < 4; ks++) {
            uint32_t af[4][4];
            #pragma unroll
            for (int mi = 0; mi < 4; mi++) {
                int row = warp_m * 64 + mi * 16 + aRowL;
                uint32_t addr = stgA + ((uint32_t)row << 7)
                              + ((uint32_t)((ks * 2 + aChunk0) ^ x7) << 4);
                ldsm4(af[mi][0], af[mi][1], af[mi][2], af[mi][3], addr);
            }
            uint32_t bf[8][2];
            #pragma unroll
            for (int nb = 0; nb < 4; nb++) {
                int row = warp_n * 64 + nb * 16 + bRowL;
                uint32_t addr = stgB + ((uint32_t)row << 7)
                              + ((uint32_t)((ks * 2 + bChunk0) ^ x7) << 4);
                uint32_t r0, r1, r2, r3;
                ldsm4(r0, r1, r2, r3, addr);
                bf[nb * 2][0] = r0; bf[nb * 2][1] = r1;
                bf[nb * 2 + 1][0] = r2; bf[nb * 2 + 1][1] = r3;
            }
            #pragma unroll
            for (int mi = 0; mi < 4; mi++)
                #pragma unroll
                for (int ni = 0; ni < 8; ni++)
                    mma_tf32(acc[mi][ni], af[mi], bf[ni]);
        }
    }

    // ---- epilogue ----
    const int erow = lane >> 2;
    const int ecol = 2 * (lane & 3);
    #pragma unroll
    for (int mi = 0; mi < 4; mi++) {
        #pragma unroll
        for (int ni = 0; ni < 8; ni++) {
            int mbase = m0 + warp_m * 64 + mi * 16 + erow;
            int nn = n0 + warp_n * 64 + ni * 8 + ecol;
            #pragma unroll
            for (int h = 0; h < 2; h++) {
                int m = mbase + h * 8;
                float v0 = acc[mi][ni][h * 2 + 0];
                float v1 = acc[mi][ni][h * 2 + 1];
                if (EPI == 3) {
                    v0 *= alpha; v1 *= alpha;
                } else {
                    float2 bb = *(const float2*)(bias + nn);
                    v0 += bb.x; v1 += bb.y;
                    if (EPI == 1) {
                        v0 = 0.5f * v0 * (1.0f + erff(v0 * 0.70710678118654752f));
                        v1 = 0.5f * v1 * (1.0f + erff(v1 * 0.70710678118654752f));
                    }
                }
                float* cp = C + (long long)m * ldc + nn;
                if (EPI == 2) {
                    float2 cv = *(const float2*)cp;
                    v0 += cv.x; v1 += cv.y;
                }
                if (RND) { v0 = rnd_tf32(v0); v1 = rnd_tf32(v1); }
                float2 o; o.x = v0; o.y = v1;
                *(float2*)cp = o;
            }
        }
    }
}

// ---------------- elementwise / reductions ----------------
__device__ __forceinline__ float warpSum(float v) {
    #pragma unroll
    for (int o = 16; o > 0; o >>= 1) v += __shfl_xor_sync(0xffffffffu, v, o);
    return v;
}
__device__ __forceinline__ float warpMax(float v) {
    #pragma unroll
    for (int o = 16; o > 0; o >>= 1) v = fmaxf(v, __shfl_xor_sync(0xffffffffu, v, o));
    return v;
}
__device__ __forceinline__ float blockSum(float v) {
    __shared__ float sh[8];
    int w = threadIdx.x >> 5, l = threadIdx.x & 31;
    v = warpSum(v);
    __syncthreads();
    if (l == 0) sh[w] = v;
    __syncthreads();
    float t = 0.f;
    #pragma unroll
    for (int i = 0; i < 8; i++) t += sh[i];
    return t;
}
__device__ __forceinline__ float blockMax(float v) {
    __shared__ float sh[8];
    int w = threadIdx.x >> 5, l = threadIdx.x & 31;
    v = warpMax(v);
    __syncthreads();
    if (l == 0) sh[w] = v;
    __syncthreads();
    float t = -INFINITY;
    #pragma unroll
    for (int i = 0; i < 8; i++) t = fmaxf(t, sh[i]);
    return t;
}

__global__ void copy4_kernel(const float4* __restrict__ src, float4* __restrict__ dst, int n4) {
    int i = blockIdx.x * 256 + threadIdx.x;
    if (i < n4) dst[i] = src[i];
}

// round float4 stream to tf32 (for weights)
__global__ void round4_kernel(const float4* __restrict__ src, float4* __restrict__ dst, int n4) {
    int i = blockIdx.x * 256 + threadIdx.x;
    if (i < n4) {
        float4 v = src[i];
        v.x = rnd_tf32(v.x); v.y = rnd_tf32(v.y);
        v.z = rnd_tf32(v.z); v.w = rnd_tf32(v.w);
        dst[i] = v;
    }
}

__global__ void __launch_bounds__(256) ln_kernel(
    const float* __restrict__ x, const float* __restrict__ w,
    const float* __restrict__ b, float* __restrict__ out)
{
    size_t row = blockIdx.x;
    const float4* xr = (const float4*)(x + row * C_);
    int tid = threadIdx.x;
    float4 v = xr[tid];
    float s = blockSum(v.x + v.y + v.z + v.w);
    float mean = s * (1.0f / C_);
    float d0 = v.x - mean, d1 = v.y - mean, d2 = v.z - mean, d3 = v.w - mean;
    float q = blockSum(d0*d0 + d1*d1 + d2*d2 + d3*d3);
    float inv = rsqrtf(q * (1.0f / C_) + 1e-5f);
    float4 wv = ((const float4*)w)[tid];
    float4 bv = ((const float4*)b)[tid];
    float4 o;
    o.x = rnd_tf32(d0 * inv * wv.x + bv.x);
    o.y = rnd_tf32(d1 * inv * wv.y + bv.y);
    o.z = rnd_tf32(d2 * inv * wv.z + bv.z);
    o.w = rnd_tf32(d3 * inv * wv.w + bv.w);
    ((float4*)(out + row * C_))[tid] = o;
}

__global__ void __launch_bounds__(256) softmax_kernel(float* __restrict__ att)
{
    int r = blockIdx.x;
    int b = r >> 11;
    int t = r & (T_ - 1);
    float* row = att + ((size_t)b * T_ + t) * T_;
    int n = t + 1;                        // valid entries
    int nw = (n + 127) & ~127;            // zero-fill through causal 128-boundary
    int tid = threadIdx.x;
    float vals[8];
    float vmax = -INFINITY;
    #pragma unroll
    for (int it = 0; it < 8; it++) {
        int i = tid + it * 256;
        vals[it] = (i < n) ? row[i] : -INFINITY;
        vmax = fmaxf(vmax, vals[it]);
    }
    vmax = blockMax(vmax);
    float s = 0.f;
    #pragma unroll
    for (int it = 0; it < 8; it++) {
        int i = tid + it * 256;
        if (i < n) { vals[it] = expf(vals[it] - vmax); s += vals[it]; }
        else vals[it] = 0.f;
    }
    s = blockSum(s);
    float inv = 1.0f / s;
    #pragma unroll
    for (int it = 0; it < 8; it++) {
        int i = tid + it * 256;
        if (i < nw) row[i] = rnd_tf32(vals[it] * inv);   // zeros stay zero
    }
}

// v[b][t][c] (inside qkv, offset 2C, row stride 3C) -> vt[b][c][t]
__global__ void transpose_v_kernel(const float* __restrict__ qkv, float* __restrict__ vt)
{
    __shared__ float tile[32][33];
    int b = blockIdx.z;
    int t0 = blockIdx.x * 32, c0 = blockIdx.y * 32;
    int tx = threadIdx.x, ty = threadIdx.y;   // 32 x 8
    #pragma unroll
    for (int r = 0; r < 32; r += 8)
        tile[ty + r][tx] = qkv[((long long)b * T_ + t0 + ty + r) * 3 * C_ + 2 * C_ + c0 + tx];
    __syncthreads();
    #pragma unroll
    for (int r = 0; r < 32; r += 8)
        vt[((long long)b * C_ + c0 + ty + r) * T_ + t0 + tx] = tile[tx][ty + r];
}

// ---------------- host launcher ----------------
extern "C" void kernel_launch(void* const* d_in, const int* in_sizes, int n_in,
                              void* d_out, int out_size)
{
    const float* x     = (const float*)d_in[0];
    const float* ln1_w = (const float*)d_in[1];
    const float* ln1_b = (const float*)d_in[2];
    const float* qkv_w = (const float*)d_in[3];
    const float* qkv_b = (const float*)d_in[4];
    const float* out_w = (const float*)d_in[5];
    const float* out_b = (const float*)d_in[6];
    const float* ln2_w = (const float*)d_in[7];
    const float* ln2_b = (const float*)d_in[8];
    const float* ff0_w = (const float*)d_in[9];
    const float* ff0_b = (const float*)d_in[10];
    const float* ff3_w = (const float*)d_in[11];
    const float* ff3_b = (const float*)d_in[12];

    float *gx, *gh, *gqkv, *gatt, *gao, *gvt, *gff;
    float *wqkv, *wout, *wff0, *wff3;
    cudaGetSymbolAddress((void**)&gx,   g_x);
    cudaGetSymbolAddress((void**)&gh,   g_h);
    cudaGetSymbolAddress((void**)&gqkv, g_qkv);
    cudaGetSymbolAddress((void**)&gatt, g_att);
    cudaGetSymbolAddress((void**)&gao,  g_ao);
    cudaGetSymbolAddress((void**)&gvt,  g_vt);
    cudaGetSymbolAddress((void**)&gff,  g_ff);
    cudaGetSymbolAddress((void**)&wqkv, g_wqkv);
    cudaGetSymbolAddress((void**)&wout, g_wout);
    cudaGetSymbolAddress((void**)&wff0, g_wff0);
    cudaGetSymbolAddress((void**)&wff3, g_wff3);

    cudaFuncSetAttribute(tc_gemm<0,false,false,true>,  cudaFuncAttributeMaxDynamicSharedMemorySize, GEMM_SMEM_BYTES);
    cudaFuncSetAttribute(tc_gemm<1,false,false,true>,  cudaFuncAttributeMaxDynamicSharedMemorySize, GEMM_SMEM_BYTES);
    cudaFuncSetAttribute(tc_gemm<2,false,false,false>, cudaFuncAttributeMaxDynamicSharedMemorySize, GEMM_SMEM_BYTES);
    cudaFuncSetAttribute(tc_gemm<3,true,false,false>,  cudaFuncAttributeMaxDynamicSharedMemorySize, GEMM_SMEM_BYTES);
    cudaFuncSetAttribute(tc_gemm<3,false,true,true>,   cudaFuncAttributeMaxDynamicSharedMemorySize, GEMM_SMEM_BYTES);

    // round all weights to tf32 once per launch
    {
        int n;
        n = 8 * 3 * C_ * C_ / 4; round4_kernel<<<(n + 255) / 256, 256>>>((const float4*)qkv_w, (float4*)wqkv, n);
        n = 8 * C_ * C_ / 4;     round4_kernel<<<(n + 255) / 256, 256>>>((const float4*)out_w, (float4*)wout, n);
        n = 8 * F_ * C_ / 4;     round4_kernel<<<(n + 255) / 256, 256>>>((const float4*)ff0_w, (float4*)wff0, n);
        n = 8 * C_ * F_ / 4;     round4_kernel<<<(n + 255) / 256, 256>>>((const float4*)ff3_w, (float4*)wff3, n);
    }

    const int n4 = MROWS * C_ / 4;
    copy4_kernel<<<(n4 + 255) / 256, 256>>>((const float4*)x, (float4*)gx, n4);

    const float scale = 0.03125f;   // 1/sqrt(1024)

    for (int i = 0; i < 8; i++) {
        // LN1 (rounded output)
        ln_kernel<<<MROWS, 256>>>(gx, ln1_w + (size_t)i * C_, ln1_b + (size_t)i * C_, gh);
        // qkv = h @ qkv_w^T + qkv_b  (rounded output)
        tc_gemm<0,false,false,true><<<dim3(3*C_/128, MROWS/128), 128, GEMM_SMEM_BYTES>>>(
            gh, wqkv + (size_t)i * 3 * C_ * C_, qkv_b + (size_t)i * 3 * C_, gqkv,
            C_, C_, C_, 3*C_, 0, 0, 0, 1.0f);
        // scores = (q @ k^T) * scale  (softmax rounds later)
        tc_gemm<3,true,false,false><<<dim3(T_/128, T_/128, B_), 128, GEMM_SMEM_BYTES>>>(
            gqkv, gqkv + C_, (const float*)0, gatt,
            C_, 3*C_, 3*C_, T_,
            (long long)T_ * 3 * C_, (long long)T_ * 3 * C_, (long long)T_ * T_, scale);
        // causal softmax (rounded output, zeros through 128-boundary)
        softmax_kernel<<<MROWS, 256>>>(gatt);
        // v^T per batch (input already rounded)
        transpose_v_kernel<<<dim3(T_/32, C_/32, B_), dim3(32, 8)>>>(gqkv, gvt);
        // ao = att @ v  (NT with B=vt, K clipped; rounded output)
        tc_gemm<3,false,true,true><<<dim3(C_/128, T_/128, B_), 128, GEMM_SMEM_BYTES>>>(
            gatt, gvt, (const float*)0, gao,
            T_, T_, T_, C_,
            (long long)T_ * T_, (long long)C_ * T_, (long long)T_ * C_, 1.0f);
        // x += ao @ out_w^T + out_b  (full fp32 residual)
        tc_gemm<2,false,false,false><<<dim3(C_/128, MROWS/128), 128, GEMM_SMEM_BYTES>>>(
            gao, wout + (size_t)i * C_ * C_, out_b + (size_t)i * C_, gx,
            C_, C_, C_, C_, 0, 0, 0, 1.0f);
        // LN2 (rounded output)
        ln_kernel<<<MROWS, 256>>>(gx, ln2_w + (size_t)i * C_, ln2_b + (size_t)i * C_, gh);
        // ff = gelu(h2 @ ff0_w^T + ff0_b)  (rounded output)
        tc_gemm<1,false,false,true><<<dim3(F_/128, MROWS/128), 128, GEMM_SMEM_BYTES>>>(
            gh, wff0 + (size_t)i * F_ * C_, ff0_b + (size_t)i * F_, gff,
            C_, C_, C_, F_, 0, 0, 0, 1.0f);
        // x += ff @ ff3_w^T + ff3_b  (full fp32 residual)
        tc_gemm<2,false,false,false><<<dim3(C_/128, MROWS/128), 128, GEMM_SMEM_BYTES>>>(
            gff, wff3 + (size_t)i * C_ * F_, ff3_b + (size_t)i * C_, gx,
            F_, F_, F_, C_, 0, 0, 0, 1.0f);
    }

    copy4_kernel<<<(n4 + 255) / 256, 256>>>((const float4*)gx, (float4*)d_out, n4);
}